// round 5
// baseline (speedup 1.0000x reference)
#include <cuda_runtime.h>
#include <cstddef>

#define D1 128
#define D2 64
#define MAXN 50176
#define MAXE 1048576
#define SCAN_B 1024

// Scratch (allocation-free rule: __device__ globals)
__device__ float g_h1  [MAXN * D1];   // (x @ W1) * dis[row]
__device__ float g_agg1[MAXN * D1];   // relu'd layer-1 output = layer-2 input
__device__ float g_h2  [MAXN * D2];   // (agg1 @ W2) * dis[row]
__device__ int   g_deg [MAXN];
__device__ float g_dis [MAXN];
__device__ int   g_scan[MAXN];        // per-chunk inclusive scan of deg
__device__ int   g_bsum[MAXN / SCAN_B + 2];
__device__ int   g_off [MAXN + 1];    // CSR offsets (by destination)
__device__ int   g_cnt [MAXN];        // fill counters
__device__ int   g_csr [MAXE];        // source node ids, sorted by destination

// ---------------------------------------------------------------------------
__global__ void zero_kernel(int n) {
    int i = blockIdx.x * blockDim.x + threadIdx.x;
    if (i < n) { g_deg[i] = 0; g_cnt[i] = 0; }
}

__global__ void deg_kernel(const int* __restrict__ col, int E) {
    int e = blockIdx.x * blockDim.x + threadIdx.x;
    if (e < E) atomicAdd(&g_deg[col[e]], 1);
}

// ---------------------------------------------------------------------------
// Exclusive scan of g_deg -> g_off  (3 small kernels); scan1 also emits dis.
// ---------------------------------------------------------------------------
__global__ void scan1_kernel(int n) {             // 1024 threads/block
    __shared__ int sh[SCAN_B];
    int t = threadIdx.x;
    int i = blockIdx.x * SCAN_B + t;
    int v = (i < n) ? g_deg[i] : 0;
    if (i < n) g_dis[i] = rsqrtf((float)(v + 1));
    sh[t] = v;
    __syncthreads();
#pragma unroll
    for (int d = 1; d < SCAN_B; d <<= 1) {
        int a = (t >= d) ? sh[t - d] : 0;
        __syncthreads();
        sh[t] += a;
        __syncthreads();
    }
    if (i < n) g_scan[i] = sh[t];                 // inclusive within chunk
    if (t == SCAN_B - 1) g_bsum[blockIdx.x] = sh[t];
}

__global__ void scan2_kernel(int nb) {            // single block, 1024 threads
    __shared__ int sh[SCAN_B];
    int t = threadIdx.x;
    int v = (t < nb) ? g_bsum[t] : 0;
    sh[t] = v;
    __syncthreads();
#pragma unroll
    for (int d = 1; d < SCAN_B; d <<= 1) {
        int a = (t >= d) ? sh[t - d] : 0;
        __syncthreads();
        sh[t] += a;
        __syncthreads();
    }
    if (t < nb) g_bsum[t] = sh[t] - v;            // exclusive
}

__global__ void scan3_kernel(int n, int E) {
    int i = blockIdx.x * blockDim.x + threadIdx.x;
    if (i < n) g_off[i] = g_scan[i] - g_deg[i] + g_bsum[i / SCAN_B];
    if (i == n) g_off[n] = E;
}

__global__ void fill_kernel(const int* __restrict__ row, const int* __restrict__ col, int E) {
    int e = blockIdx.x * blockDim.x + threadIdx.x;
    if (e >= E) return;
    int c = col[e];
    int pos = g_off[c] + atomicAdd(&g_cnt[c], 1);
    g_csr[pos] = row[e];
}

// ---------------------------------------------------------------------------
// SGEMM: H[n, BN] = (X[n, 128] @ W[128, BN]) * dis[row]
// 256 threads, 8x8 register tile, double-buffered smem + register prefetch.
// LAYER=1: X = x (param), H = g_h1.  LAYER=2: X = g_agg1, H = g_h2.
// ---------------------------------------------------------------------------
template <int BM, int BN, int BK, int LAYER>
__global__ void __launch_bounds__(256, 2)
sgemm_kernel(const float* __restrict__ Xp, const float* __restrict__ W, int n) {
    constexpr int K = 128;
    constexpr int NT = K / BK;
    constexpr int NTHREADS = 256;
    constexpr int XS = BM + 4;
    constexpr int XLD = BM * BK / 4 / NTHREADS;
    constexpr int WLD = BK * BN / 4 / NTHREADS;
    constexpr int KG = BK / 4;

    __shared__ float Xs[2][BK * XS];
    __shared__ float Ws[2][BK * BN];

    const float* X = (LAYER == 1) ? Xp : g_agg1;
    float*       H = (LAYER == 1) ? g_h1 : g_h2;

    int tid = threadIdx.x;
    constexpr int TXN = BN / 8;
    int tx = tid % TXN;
    int ty = tid / TXN;
    int row0 = blockIdx.x * BM;

    float acc[8][8];
#pragma unroll
    for (int i = 0; i < 8; i++)
#pragma unroll
        for (int j = 0; j < 8; j++) acc[i][j] = 0.f;

    float4 px[XLD], pw[WLD];
    const float4 z4 = make_float4(0.f, 0.f, 0.f, 0.f);

    auto loadX = [&](int k0) {
#pragma unroll
        for (int l = 0; l < XLD; l++) {
            int idx = tid + l * NTHREADS;
            int r = idx / KG;
            int kk4 = (idx % KG) * 4;
            int gr = row0 + r;
            px[l] = (gr < n) ? *(const float4*)(X + (size_t)gr * K + k0 + kk4) : z4;
        }
    };
    auto loadW = [&](int k0) {
#pragma unroll
        for (int l = 0; l < WLD; l++) {
            int idx = (tid + l * NTHREADS) * 4;
            int kk = idx / BN, c = idx % BN;
            pw[l] = *(const float4*)(W + (size_t)(k0 + kk) * BN + c);
        }
    };
    auto storeX = [&](int buf) {
#pragma unroll
        for (int l = 0; l < XLD; l++) {
            int idx = tid + l * NTHREADS;
            int r = idx / KG;
            int kk4 = (idx % KG) * 4;
            Xs[buf][(kk4 + 0) * XS + r] = px[l].x;
            Xs[buf][(kk4 + 1) * XS + r] = px[l].y;
            Xs[buf][(kk4 + 2) * XS + r] = px[l].z;
            Xs[buf][(kk4 + 3) * XS + r] = px[l].w;
        }
    };
    auto storeW = [&](int buf) {
#pragma unroll
        for (int l = 0; l < WLD; l++) {
            int idx = (tid + l * NTHREADS) * 4;
            int kk = idx / BN, c = idx % BN;
            *(float4*)(Ws[buf] + kk * BN + c) = pw[l];
        }
    };

    loadX(0); loadW(0);
    storeX(0); storeW(0);
    __syncthreads();

#pragma unroll
    for (int t = 0; t < NT; t++) {
        int cur = t & 1;
        if (t + 1 < NT) { loadX((t + 1) * BK); loadW((t + 1) * BK); }
#pragma unroll
        for (int kk = 0; kk < BK; kk++) {
            float a[8], b[8];
            *(float4*)&a[0] = *(const float4*)(Xs[cur] + kk * XS + ty * 8);
            *(float4*)&a[4] = *(const float4*)(Xs[cur] + kk * XS + ty * 8 + 4);
            *(float4*)&b[0] = *(const float4*)(Ws[cur] + kk * BN + tx * 4);
            *(float4*)&b[4] = *(const float4*)(Ws[cur] + kk * BN + BN / 2 + tx * 4);
#pragma unroll
            for (int i = 0; i < 8; i++)
#pragma unroll
                for (int j = 0; j < 8; j++) acc[i][j] = fmaf(a[i], b[j], acc[i][j]);
        }
        if (t + 1 < NT) {
            storeX(cur ^ 1); storeW(cur ^ 1);   // other buffer: no race with readers
            __syncthreads();
        }
    }

#pragma unroll
    for (int i = 0; i < 8; i++) {
        int gr = row0 + ty * 8 + i;
        if (gr < n) {
            float d = g_dis[gr];
            float4 v0 = make_float4(acc[i][0] * d, acc[i][1] * d, acc[i][2] * d, acc[i][3] * d);
            float4 v1 = make_float4(acc[i][4] * d, acc[i][5] * d, acc[i][6] * d, acc[i][7] * d);
            *(float4*)(H + (size_t)gr * BN + tx * 4)          = v0;
            *(float4*)(H + (size_t)gr * BN + BN / 2 + tx * 4) = v1;
        }
    }
}

// ---------------------------------------------------------------------------
// Gather, layer 1: warp per node, lane covers 4 of 128 floats.
// agg1[c] = relu(dis[c] * (sum_{r in N(c)} h1[r] + h1[c]) + b1)
// ---------------------------------------------------------------------------
__global__ void gather1_kernel(const float* __restrict__ b1, int n) {
    int w = (blockIdx.x * blockDim.x + threadIdx.x) >> 5;
    if (w >= n) return;
    int lane = threadIdx.x & 31;
    int s = g_off[w], e = g_off[w + 1];
    const float4* h = (const float4*)g_h1;
    float4 a0 = make_float4(0.f, 0.f, 0.f, 0.f), a1 = a0;
    int i = s;
    for (; i + 1 < e; i += 2) {
        int r0 = __ldg(g_csr + i), r1 = __ldg(g_csr + i + 1);
        float4 v0 = h[(size_t)r0 * 32 + lane];
        float4 v1 = h[(size_t)r1 * 32 + lane];
        a0.x += v0.x; a0.y += v0.y; a0.z += v0.z; a0.w += v0.w;
        a1.x += v1.x; a1.y += v1.y; a1.z += v1.z; a1.w += v1.w;
    }
    if (i < e) {
        int r0 = __ldg(g_csr + i);
        float4 v0 = h[(size_t)r0 * 32 + lane];
        a0.x += v0.x; a0.y += v0.y; a0.z += v0.z; a0.w += v0.w;
    }
    float4 sv = h[(size_t)w * 32 + lane];
    float d = g_dis[w];
    float4 b = ((const float4*)b1)[lane];
    float4 r;
    r.x = fmaxf(fmaf(a0.x + a1.x + sv.x, d, b.x), 0.f);
    r.y = fmaxf(fmaf(a0.y + a1.y + sv.y, d, b.y), 0.f);
    r.z = fmaxf(fmaf(a0.z + a1.z + sv.z, d, b.z), 0.f);
    r.w = fmaxf(fmaf(a0.w + a1.w + sv.w, d, b.w), 0.f);
    ((float4*)g_agg1)[(size_t)w * 32 + lane] = r;
}

// Gather, layer 2: warp per node, lane covers 2 of 64 floats -> d_out.
__global__ void gather2_kernel(const float* __restrict__ b2, float* __restrict__ dout, int n) {
    int w = (blockIdx.x * blockDim.x + threadIdx.x) >> 5;
    if (w >= n) return;
    int lane = threadIdx.x & 31;
    int s = g_off[w], e = g_off[w + 1];
    const float2* h = (const float2*)g_h2;
    float2 a0 = make_float2(0.f, 0.f), a1 = a0;
    int i = s;
    for (; i + 1 < e; i += 2) {
        int r0 = __ldg(g_csr + i), r1 = __ldg(g_csr + i + 1);
        float2 v0 = h[(size_t)r0 * 32 + lane];
        float2 v1 = h[(size_t)r1 * 32 + lane];
        a0.x += v0.x; a0.y += v0.y;
        a1.x += v1.x; a1.y += v1.y;
    }
    if (i < e) {
        int r0 = __ldg(g_csr + i);
        float2 v0 = h[(size_t)r0 * 32 + lane];
        a0.x += v0.x; a0.y += v0.y;
    }
    float2 sv = h[(size_t)w * 32 + lane];
    float d = g_dis[w];
    float2 b = ((const float2*)b2)[lane];
    float2 r;
    r.x = fmaf(a0.x + a1.x + sv.x, d, b.x);
    r.y = fmaf(a0.y + a1.y + sv.y, d, b.y);
    ((float2*)dout)[(size_t)w * 32 + lane] = r;
}

// ---------------------------------------------------------------------------
extern "C" void kernel_launch(void* const* d_in, const int* in_sizes, int n_in,
                              void* d_out, int out_size) {
    const float* x  = (const float*)d_in[0];
    const int*   ei = (const int*)  d_in[1];
    const float* W1 = (const float*)d_in[2];
    const float* b1 = (const float*)d_in[3];
    const float* W2 = (const float*)d_in[4];
    const float* b2 = (const float*)d_in[5];
    float* out = (float*)d_out;

    int n = in_sizes[0] / D1;
    int E = in_sizes[1] / 2;
    const int* row = ei;
    const int* col = ei + E;
    int nb = (n + SCAN_B - 1) / SCAN_B;

    const int TB = 256;
    zero_kernel<<<(n + TB - 1) / TB, TB>>>(n);
    deg_kernel<<<(E + TB - 1) / TB, TB>>>(col, E);

    scan1_kernel<<<nb, SCAN_B>>>(n);
    scan2_kernel<<<1, SCAN_B>>>(nb);
    scan3_kernel<<<(n + 1 + TB - 1) / TB, TB>>>(n, E);
    fill_kernel<<<(E + TB - 1) / TB, TB>>>(row, col, E);

    sgemm_kernel<128, 128, 16, 1><<<(n + 127) / 128, TB>>>(x, W1, n);
    gather1_kernel<<<(n * 32 + TB - 1) / TB, TB>>>(b1, n);

    sgemm_kernel<256, 64, 16, 2><<<(n + 255) / 256, TB>>>(nullptr, W2, n);
    gather2_kernel<<<(n * 32 + TB - 1) / TB, TB>>>(b2, out, n);
}

// round 6
// speedup vs baseline: 1.2098x; 1.2098x over previous
#include <cuda_runtime.h>
#include <cstddef>

#define D1 128
#define D2 64
#define MAXN 50176
#define MAXE 1048576
#define SCAN_B 1024

// Scratch (allocation-free rule: __device__ globals)
__device__ float g_h1  [MAXN * D1];   // (x @ W1) * dis[row]
__device__ float g_agg1[MAXN * D1];   // relu'd layer-1 output = layer-2 input
__device__ float g_h2  [MAXN * D2];   // (agg1 @ W2) * dis[row]
__device__ int   g_deg [MAXN];
__device__ float g_dis [MAXN];
__device__ int   g_scan[MAXN];        // per-chunk inclusive scan of deg
__device__ int   g_bsum[MAXN / SCAN_B + 2];
__device__ int   g_off [MAXN + 1];    // CSR offsets (by destination)
__device__ int   g_cnt [MAXN];        // fill counters
__device__ int   g_csr [MAXE];        // source node ids, sorted by destination

// ---------------------------------------------------------------------------
__global__ void zero_kernel(int n) {
    int i = blockIdx.x * blockDim.x + threadIdx.x;
    if (i < n) { g_deg[i] = 0; g_cnt[i] = 0; }
}

__global__ void deg_kernel(const int* __restrict__ col, int E) {
    int e = blockIdx.x * blockDim.x + threadIdx.x;
    if (e < E) atomicAdd(&g_deg[col[e]], 1);
}

// ---------------------------------------------------------------------------
// Exclusive scan of g_deg -> g_off  (3 small kernels); scan1 also emits dis.
// ---------------------------------------------------------------------------
__global__ void scan1_kernel(int n) {             // 1024 threads/block
    __shared__ int sh[SCAN_B];
    int t = threadIdx.x;
    int i = blockIdx.x * SCAN_B + t;
    int v = (i < n) ? g_deg[i] : 0;
    if (i < n) g_dis[i] = rsqrtf((float)(v + 1));
    sh[t] = v;
    __syncthreads();
#pragma unroll
    for (int d = 1; d < SCAN_B; d <<= 1) {
        int a = (t >= d) ? sh[t - d] : 0;
        __syncthreads();
        sh[t] += a;
        __syncthreads();
    }
    if (i < n) g_scan[i] = sh[t];                 // inclusive within chunk
    if (t == SCAN_B - 1) g_bsum[blockIdx.x] = sh[t];
}

__global__ void scan2_kernel(int nb) {            // single block, 1024 threads
    __shared__ int sh[SCAN_B];
    int t = threadIdx.x;
    int v = (t < nb) ? g_bsum[t] : 0;
    sh[t] = v;
    __syncthreads();
#pragma unroll
    for (int d = 1; d < SCAN_B; d <<= 1) {
        int a = (t >= d) ? sh[t - d] : 0;
        __syncthreads();
        sh[t] += a;
        __syncthreads();
    }
    if (t < nb) g_bsum[t] = sh[t] - v;            // exclusive
}

__global__ void scan3_kernel(int n, int E) {
    int i = blockIdx.x * blockDim.x + threadIdx.x;
    if (i < n) g_off[i] = g_scan[i] - g_deg[i] + g_bsum[i / SCAN_B];
    if (i == n) g_off[n] = E;
}

__global__ void fill_kernel(const int* __restrict__ row, const int* __restrict__ col, int E) {
    int e = blockIdx.x * blockDim.x + threadIdx.x;
    if (e >= E) return;
    int c = col[e];
    int pos = g_off[c] + atomicAdd(&g_cnt[c], 1);
    g_csr[pos] = row[e];
}

// ---------------------------------------------------------------------------
// SGEMM: H[n, BN] = (X[n, 128] @ W[128, BN]) * dis[row]
// 256 threads, 8x8 register tile, single-buffer smem, register prefetch.
// (R4 version — double-buffer + outer unroll regressed via register spills.)
// ---------------------------------------------------------------------------
template <int BM, int BN, int BK, int LAYER>
__global__ void __launch_bounds__(256, 2)
sgemm_kernel(const float* __restrict__ Xp, const float* __restrict__ W, int n) {
    constexpr int K = 128;
    constexpr int NT = K / BK;
    constexpr int NTHREADS = 256;
    constexpr int XS = BM + 4;
    constexpr int XLD = BM * BK / 4 / NTHREADS;
    constexpr int WLD = BK * BN / 4 / NTHREADS;
    constexpr int KG = BK / 4;

    __shared__ float Xs[BK * XS];
    __shared__ float Ws[BK * BN];

    const float* X = (LAYER == 1) ? Xp : g_agg1;
    float*       H = (LAYER == 1) ? g_h1 : g_h2;

    int tid = threadIdx.x;
    constexpr int TXN = BN / 8;
    int tx = tid % TXN;
    int ty = tid / TXN;
    int row0 = blockIdx.x * BM;

    float acc[8][8];
#pragma unroll
    for (int i = 0; i < 8; i++)
#pragma unroll
        for (int j = 0; j < 8; j++) acc[i][j] = 0.f;

    float4 px[XLD], pw[WLD];
    const float4 z4 = make_float4(0.f, 0.f, 0.f, 0.f);

    auto loadX = [&](int k0) {
#pragma unroll
        for (int l = 0; l < XLD; l++) {
            int idx = tid + l * NTHREADS;
            int r = idx / KG;
            int kk4 = (idx % KG) * 4;
            int gr = row0 + r;
            px[l] = (gr < n) ? *(const float4*)(X + (size_t)gr * K + k0 + kk4) : z4;
        }
    };
    auto loadW = [&](int k0) {
#pragma unroll
        for (int l = 0; l < WLD; l++) {
            int idx = (tid + l * NTHREADS) * 4;
            int kk = idx / BN, c = idx % BN;
            pw[l] = *(const float4*)(W + (size_t)(k0 + kk) * BN + c);
        }
    };
    auto storeX = [&]() {
#pragma unroll
        for (int l = 0; l < XLD; l++) {
            int idx = tid + l * NTHREADS;
            int r = idx / KG;
            int kk4 = (idx % KG) * 4;
            Xs[(kk4 + 0) * XS + r] = px[l].x;
            Xs[(kk4 + 1) * XS + r] = px[l].y;
            Xs[(kk4 + 2) * XS + r] = px[l].z;
            Xs[(kk4 + 3) * XS + r] = px[l].w;
        }
    };
    auto storeW = [&]() {
#pragma unroll
        for (int l = 0; l < WLD; l++) {
            int idx = (tid + l * NTHREADS) * 4;
            int kk = idx / BN, c = idx % BN;
            *(float4*)(Ws + kk * BN + c) = pw[l];
        }
    };

    loadX(0); loadW(0);
    storeX(); storeW();
    __syncthreads();

    for (int t = 0; t < NT; t++) {
        if (t + 1 < NT) { loadX((t + 1) * BK); loadW((t + 1) * BK); }
#pragma unroll
        for (int kk = 0; kk < BK; kk++) {
            float a[8], b[8];
            *(float4*)&a[0] = *(const float4*)(Xs + kk * XS + ty * 8);
            *(float4*)&a[4] = *(const float4*)(Xs + kk * XS + ty * 8 + 4);
            *(float4*)&b[0] = *(const float4*)(Ws + kk * BN + tx * 4);
            *(float4*)&b[4] = *(const float4*)(Ws + kk * BN + BN / 2 + tx * 4);
#pragma unroll
            for (int i = 0; i < 8; i++)
#pragma unroll
                for (int j = 0; j < 8; j++) acc[i][j] = fmaf(a[i], b[j], acc[i][j]);
        }
        if (t + 1 < NT) {
            __syncthreads();
            storeX(); storeW();
            __syncthreads();
        }
    }

#pragma unroll
    for (int i = 0; i < 8; i++) {
        int gr = row0 + ty * 8 + i;
        if (gr < n) {
            float d = g_dis[gr];
            float4 v0 = make_float4(acc[i][0] * d, acc[i][1] * d, acc[i][2] * d, acc[i][3] * d);
            float4 v1 = make_float4(acc[i][4] * d, acc[i][5] * d, acc[i][6] * d, acc[i][7] * d);
            *(float4*)(H + (size_t)gr * BN + tx * 4)          = v0;
            *(float4*)(H + (size_t)gr * BN + BN / 2 + tx * 4) = v1;
        }
    }
}

// ---------------------------------------------------------------------------
// Gather, layer 1: warp per node, lane covers 4 of 128 floats; 4-way MLP.
// agg1[c] = relu(dis[c] * (sum_{r in N(c)} h1[r] + h1[c]) + b1)
// ---------------------------------------------------------------------------
__global__ void gather1_kernel(const float* __restrict__ b1, int n) {
    int w = (blockIdx.x * blockDim.x + threadIdx.x) >> 5;
    if (w >= n) return;
    int lane = threadIdx.x & 31;
    int s = g_off[w], e = g_off[w + 1];
    const float4* h = (const float4*)g_h1;
    float4 a0 = make_float4(0.f, 0.f, 0.f, 0.f), a1 = a0, a2 = a0, a3 = a0;
    int i = s;
    for (; i + 3 < e; i += 4) {
        int r0 = __ldg(g_csr + i),     r1 = __ldg(g_csr + i + 1);
        int r2 = __ldg(g_csr + i + 2), r3 = __ldg(g_csr + i + 3);
        float4 v0 = h[(size_t)r0 * 32 + lane];
        float4 v1 = h[(size_t)r1 * 32 + lane];
        float4 v2 = h[(size_t)r2 * 32 + lane];
        float4 v3 = h[(size_t)r3 * 32 + lane];
        a0.x += v0.x; a0.y += v0.y; a0.z += v0.z; a0.w += v0.w;
        a1.x += v1.x; a1.y += v1.y; a1.z += v1.z; a1.w += v1.w;
        a2.x += v2.x; a2.y += v2.y; a2.z += v2.z; a2.w += v2.w;
        a3.x += v3.x; a3.y += v3.y; a3.z += v3.z; a3.w += v3.w;
    }
    for (; i < e; i++) {
        int r0 = __ldg(g_csr + i);
        float4 v0 = h[(size_t)r0 * 32 + lane];
        a0.x += v0.x; a0.y += v0.y; a0.z += v0.z; a0.w += v0.w;
    }
    float4 sv = h[(size_t)w * 32 + lane];
    float d = g_dis[w];
    float4 b = ((const float4*)b1)[lane];
    float4 r;
    r.x = fmaxf(fmaf(a0.x + a1.x + a2.x + a3.x + sv.x, d, b.x), 0.f);
    r.y = fmaxf(fmaf(a0.y + a1.y + a2.y + a3.y + sv.y, d, b.y), 0.f);
    r.z = fmaxf(fmaf(a0.z + a1.z + a2.z + a3.z + sv.z, d, b.z), 0.f);
    r.w = fmaxf(fmaf(a0.w + a1.w + a2.w + a3.w + sv.w, d, b.w), 0.f);
    ((float4*)g_agg1)[(size_t)w * 32 + lane] = r;
}

// Gather, layer 2: warp per node, lane covers 2 of 64 floats -> d_out; 4-way MLP.
__global__ void gather2_kernel(const float* __restrict__ b2, float* __restrict__ dout, int n) {
    int w = (blockIdx.x * blockDim.x + threadIdx.x) >> 5;
    if (w >= n) return;
    int lane = threadIdx.x & 31;
    int s = g_off[w], e = g_off[w + 1];
    const float2* h = (const float2*)g_h2;
    float2 a0 = make_float2(0.f, 0.f), a1 = a0, a2 = a0, a3 = a0;
    int i = s;
    for (; i + 3 < e; i += 4) {
        int r0 = __ldg(g_csr + i),     r1 = __ldg(g_csr + i + 1);
        int r2 = __ldg(g_csr + i + 2), r3 = __ldg(g_csr + i + 3);
        float2 v0 = h[(size_t)r0 * 32 + lane];
        float2 v1 = h[(size_t)r1 * 32 + lane];
        float2 v2 = h[(size_t)r2 * 32 + lane];
        float2 v3 = h[(size_t)r3 * 32 + lane];
        a0.x += v0.x; a0.y += v0.y;
        a1.x += v1.x; a1.y += v1.y;
        a2.x += v2.x; a2.y += v2.y;
        a3.x += v3.x; a3.y += v3.y;
    }
    for (; i < e; i++) {
        int r0 = __ldg(g_csr + i);
        float2 v0 = h[(size_t)r0 * 32 + lane];
        a0.x += v0.x; a0.y += v0.y;
    }
    float2 sv = h[(size_t)w * 32 + lane];
    float d = g_dis[w];
    float2 b = ((const float2*)b2)[lane];
    float2 r;
    r.x = fmaf(a0.x + a1.x + a2.x + a3.x + sv.x, d, b.x);
    r.y = fmaf(a0.y + a1.y + a2.y + a3.y + sv.y, d, b.y);
    ((float2*)dout)[(size_t)w * 32 + lane] = r;
}

// ---------------------------------------------------------------------------
extern "C" void kernel_launch(void* const* d_in, const int* in_sizes, int n_in,
                              void* d_out, int out_size) {
    const float* x  = (const float*)d_in[0];
    const int*   ei = (const int*)  d_in[1];
    const float* W1 = (const float*)d_in[2];
    const float* b1 = (const float*)d_in[3];
    const float* W2 = (const float*)d_in[4];
    const float* b2 = (const float*)d_in[5];
    float* out = (float*)d_out;

    int n = in_sizes[0] / D1;
    int E = in_sizes[1] / 2;
    const int* row = ei;
    const int* col = ei + E;
    int nb = (n + SCAN_B - 1) / SCAN_B;

    const int TB = 256;
    zero_kernel<<<(n + TB - 1) / TB, TB>>>(n);
    deg_kernel<<<(E + TB - 1) / TB, TB>>>(col, E);

    scan1_kernel<<<nb, SCAN_B>>>(n);
    scan2_kernel<<<1, SCAN_B>>>(nb);
    scan3_kernel<<<(n + 1 + TB - 1) / TB, TB>>>(n, E);
    fill_kernel<<<(E + TB - 1) / TB, TB>>>(row, col, E);

    sgemm_kernel<128, 128, 16, 1><<<(n + 127) / 128, TB>>>(x, W1, n);
    gather1_kernel<<<(n * 32 + TB - 1) / TB, TB>>>(b1, n);

    sgemm_kernel<256, 64, 16, 2><<<(n + 255) / 256, TB>>>(nullptr, W2, n);
    gather2_kernel<<<(n * 32 + TB - 1) / TB, TB>>>(b2, out, n);
}